// round 14
// baseline (speedup 1.0000x reference)
#include <cuda_runtime.h>
#include <cuda_bf16.h>

// IIR lfilter (order-8, 9 taps), DF2T, chunked parallelization.
// x: (64, 64, 8192) fp32 -> y = clip(lfilter(x, A, B), -1, 1)
//
// R13: R12's warm loop exposed DRAM latency (LDG consumed immediately,
// issue% fell to 41). This round software-pipelines the warm FIR with
// register ping-pong buffers (cur/nxt, unroll-by-2, no copies), issues the
// first warm tile's LDGs before the G-table barrier (overlaps the serial G
// computation), and prefetches the first emit tile during the last warm
// FIR. Everything else (register FIR warmup, WARM=192, NCH=32, emit phase)
// is unchanged from R12.

#define T_LEN   8192
#define M_SEQ   4096
#define NCH     32         // chunks per sequence
#define CHUNK   256        // T_LEN / NCH
#define WARM    192        // FIR taps (0.95^192 ~ 5e-5 transient)
#define TT      16         // time-tile
#define NWT     (WARM/TT)  // 12 warm tiles
#define STRIDE  130        // SMEM row stride (conflict-free under this lane map)

// One DF2T step. State z0..z7; unclamped y feeds the recurrence.
#define IIR_STEP(xv, yout)                                       \
    do {                                                         \
        float _iir_y = fmaf(b0, (xv), z0);                       \
        z0 = fmaf(-a1, _iir_y, fmaf(b1, (xv), z1));              \
        z1 = fmaf(-a2, _iir_y, fmaf(b2, (xv), z2));              \
        z2 = fmaf(-a3, _iir_y, fmaf(b3, (xv), z3));              \
        z3 = fmaf(-a4, _iir_y, fmaf(b4, (xv), z4));              \
        z4 = fmaf(-a5, _iir_y, fmaf(b5, (xv), z5));              \
        z5 = fmaf(-a6, _iir_y, fmaf(b6, (xv), z6));              \
        z6 = fmaf(-a7, _iir_y, fmaf(b7, (xv), z7));              \
        z7 = fmaf(-a8, _iir_y, b8 * (xv));                       \
        (yout) = _iir_y;                                         \
    } while (0)

// Accumulate one loaded tile (4 rows x 4 times per thread) into acc[4][8].
// buf[i] = float4 of row (rl+32i), times t+col .. t+col+3.
#define WARM_FIR(buf, tbase)                                         \
    do {                                                             \
        const int _db = tout - 1 - (tbase) - col;                    \
        _Pragma("unroll")                                            \
        for (int k = 0; k < 4; k++) {                                \
            const float4 g0 = gs03[_db - k];                         \
            const float4 g1 = gs47[_db - k];                         \
            _Pragma("unroll")                                        \
            for (int i = 0; i < 4; i++) {                            \
                const float xv =                                     \
                    reinterpret_cast<const float*>(&(buf)[i])[k];    \
                acc[i][0] = fmaf(g0.x, xv, acc[i][0]);               \
                acc[i][1] = fmaf(g0.y, xv, acc[i][1]);               \
                acc[i][2] = fmaf(g0.z, xv, acc[i][2]);               \
                acc[i][3] = fmaf(g0.w, xv, acc[i][3]);               \
                acc[i][4] = fmaf(g1.x, xv, acc[i][4]);               \
                acc[i][5] = fmaf(g1.y, xv, acc[i][5]);               \
                acc[i][6] = fmaf(g1.z, xv, acc[i][6]);               \
                acc[i][7] = fmaf(g1.w, xv, acc[i][7]);               \
            }                                                        \
        }                                                            \
    } while (0)

#define LOAD_TILE(buf, tbase)                                        \
    do {                                                             \
        _Pragma("unroll")                                            \
        for (int i = 0; i < 4; i++)                                  \
            (buf)[i] = *reinterpret_cast<const float4*>(             \
                xbase + (size_t)i * 32 * T_LEN + (tbase));           \
    } while (0)

__global__ __launch_bounds__(128, 7)
void iir_fused_kernel(const float* __restrict__ x,
                      const float* __restrict__ Ag,
                      const float* __restrict__ Bg,
                      float* __restrict__ y)
{
    __shared__ float  xs[TT * STRIDE];   // [time][seq] transpose tile
    __shared__ float  ys[TT * STRIDE];   // output tile; reused as state scratch
    __shared__ float4 gs03[WARM];        // G(d) states z0..z3
    __shared__ float4 gs47[WARM];        // G(d) states z4..z7

    const int tid   = threadIdx.x;                 // 0..127 = local sequence
    const int c     = blockIdx.x >> 5;             // chunk index (block-uniform)
    const int mbase = (blockIdx.x & 31) << 7;      // 128 sequences per block

    // Lane map for tile I/O: thread -> (row base rl, time column col).
    const int rl  = tid >> 2;           // 0..31; rows rl + 32*i
    const int cj  = tid & 3;            // 0..3
    const int col = cj << 2;            // 0,4,8,12

    const float* xbase = x + (size_t)(mbase + rl) * T_LEN + col;
    float*       ybase = y + (size_t)(mbase + rl) * T_LEN + col;

    const int tout = c * CHUNK;
    const int tend = tout + CHUNK;

    float z0 = 0.f, z1 = 0.f, z2 = 0.f, z3 = 0.f,
          z4 = 0.f, z5 = 0.f, z6 = 0.f, z7 = 0.f;

    float4 pf[4];

    if (c > 0) {
        const int tstart = tout - WARM;

        // Issue first warm tile's LDGs BEFORE the G barrier: DRAM latency
        // overlaps the serial G computation below.
        float4 cur[4], nxt[4];
        LOAD_TILE(cur, tstart);

        // G table: DF2T state impulse response, serial on thread 0.
        if (tid == 0) {
            const float ginv = 1.0f / Ag[0];
            float ga[9], gb[9];
#pragma unroll
            for (int i = 0; i < 9; i++) { ga[i] = Ag[i] * ginv; gb[i] = Bg[i] * ginv; }
            float gz[8];
            const float gy0 = gb[0];                       // impulse step
#pragma unroll
            for (int i = 0; i < 8; i++) gz[i] = gb[i + 1] - ga[i + 1] * gy0;
            gs03[0] = make_float4(gz[0], gz[1], gz[2], gz[3]);
            gs47[0] = make_float4(gz[4], gz[5], gz[6], gz[7]);
            for (int d = 1; d < WARM; d++) {
                const float yv = gz[0];                    // zero-input step
#pragma unroll
                for (int i = 0; i < 7; i++) gz[i] = gz[i + 1] - ga[i + 1] * yv;
                gz[7] = -ga[8] * yv;
                gs03[d] = make_float4(gz[0], gz[1], gz[2], gz[3]);
                gs47[d] = make_float4(gz[4], gz[5], gz[6], gz[7]);
            }
        }

        float acc[4][8];
#pragma unroll
        for (int i = 0; i < 4; i++)
#pragma unroll
            for (int s = 0; s < 8; s++) acc[i][s] = 0.f;

        __syncthreads();   // G table ready (cur LDGs already in flight)

        // Pipelined warm FIR: ping-pong cur/nxt, prefetch one tile ahead.
        for (int w = 0; w < NWT; w += 2) {
            const int t0 = tstart + w * TT;
            LOAD_TILE(nxt, t0 + TT);
            WARM_FIR(cur, t0);
            if (w + 2 < NWT) {
                LOAD_TILE(cur, t0 + 2 * TT);
            } else {
                LOAD_TILE(pf, tout);        // first emit tile
            }
            WARM_FIR(nxt, t0 + TT);
        }

        // Butterfly all-reduce across the 4 col-lanes (lanes xor 1, xor 2).
#pragma unroll
        for (int i = 0; i < 4; i++)
#pragma unroll
            for (int s = 0; s < 8; s++) {
                acc[i][s] += __shfl_xor_sync(0xFFFFFFFFu, acc[i][s], 1);
                acc[i][s] += __shfl_xor_sync(0xFFFFFFFFu, acc[i][s], 2);
            }

        // Exchange: states -> owner threads via ys scratch (ys[s][row]).
        if (cj == 0) {
#pragma unroll
            for (int i = 0; i < 4; i++)
#pragma unroll
                for (int s = 0; s < 8; s++)
                    ys[s * STRIDE + (rl + 32 * i)] = acc[i][s];
        }
        __syncthreads();
        z0 = ys[0 * STRIDE + tid];
        z1 = ys[1 * STRIDE + tid];
        z2 = ys[2 * STRIDE + tid];
        z3 = ys[3 * STRIDE + tid];
        z4 = ys[4 * STRIDE + tid];
        z5 = ys[5 * STRIDE + tid];
        z6 = ys[6 * STRIDE + tid];
        z7 = ys[7 * STRIDE + tid];

        // Stage first emit tile into xs.
#pragma unroll
        for (int i = 0; i < 4; i++) {
            const int r = rl + 32 * i;
            xs[(col + 0) * STRIDE + r] = pf[i].x;
            xs[(col + 1) * STRIDE + r] = pf[i].y;
            xs[(col + 2) * STRIDE + r] = pf[i].z;
            xs[(col + 3) * STRIDE + r] = pf[i].w;
        }
        __syncthreads();   // xs staged; all z reads done before ys is rewritten
    } else {
        // c == 0: zero state, stage tile at t=0.
        LOAD_TILE(pf, 0);
#pragma unroll
        for (int i = 0; i < 4; i++) {
            const int r = rl + 32 * i;
            xs[(col + 0) * STRIDE + r] = pf[i].x;
            xs[(col + 1) * STRIDE + r] = pf[i].y;
            xs[(col + 2) * STRIDE + r] = pf[i].z;
            xs[(col + 3) * STRIDE + r] = pf[i].w;
        }
        __syncthreads();
    }

    // Coefficients (normalized by A[0]) — loaded after warm to cut warm-phase
    // register pressure.
    const float inv = 1.0f / __ldg(&Ag[0]);
    const float a1 = __ldg(&Ag[1]) * inv;
    const float a2 = __ldg(&Ag[2]) * inv;
    const float a3 = __ldg(&Ag[3]) * inv;
    const float a4 = __ldg(&Ag[4]) * inv;
    const float a5 = __ldg(&Ag[5]) * inv;
    const float a6 = __ldg(&Ag[6]) * inv;
    const float a7 = __ldg(&Ag[7]) * inv;
    const float a8 = __ldg(&Ag[8]) * inv;
    const float b0 = __ldg(&Bg[0]) * inv;
    const float b1 = __ldg(&Bg[1]) * inv;
    const float b2 = __ldg(&Bg[2]) * inv;
    const float b3 = __ldg(&Bg[3]) * inv;
    const float b4 = __ldg(&Bg[4]) * inv;
    const float b5 = __ldg(&Bg[5]) * inv;
    const float b6 = __ldg(&Bg[6]) * inv;
    const float b7 = __ldg(&Bg[7]) * inv;
    const float b8 = __ldg(&Bg[8]) * inv;

    // ================= Emit phase: IIR over [tout, tend) =================
    for (int t = tout; t < tend; t += TT) {
        const int tp = (t + TT < tend) ? (t + TT) : tout;   // in-bounds clamp
        LOAD_TILE(pf, tp);

#pragma unroll
        for (int tt = 0; tt < TT; tt++) {
            const float xv = xs[tt * STRIDE + tid];
            float yo;
            IIR_STEP(xv, yo);
            ys[tt * STRIDE + tid] = fminf(fmaxf(yo, -1.0f), 1.0f);
        }
        __syncthreads();   // ys complete; xs consumed

        // Coalesced output of this tile.
#pragma unroll
        for (int i = 0; i < 4; i++) {
            const int r = rl + 32 * i;
            float4 v;
            v.x = ys[(col + 0) * STRIDE + r];
            v.y = ys[(col + 1) * STRIDE + r];
            v.z = ys[(col + 2) * STRIDE + r];
            v.w = ys[(col + 3) * STRIDE + r];
            *reinterpret_cast<float4*>(ybase + (size_t)i * 32 * T_LEN + t) = v;
        }

        // Stage prefetched tile.
#pragma unroll
        for (int i = 0; i < 4; i++) {
            const int r = rl + 32 * i;
            xs[(col + 0) * STRIDE + r] = pf[i].x;
            xs[(col + 1) * STRIDE + r] = pf[i].y;
            xs[(col + 2) * STRIDE + r] = pf[i].z;
            xs[(col + 3) * STRIDE + r] = pf[i].w;
        }
        __syncthreads();
    }
}

extern "C" void kernel_launch(void* const* d_in, const int* in_sizes, int n_in,
                              void* d_out, int out_size)
{
    const float* x = (const float*)d_in[0];
    const float* A = (const float*)d_in[1];
    const float* B = (const float*)d_in[2];
    float*       y = (float*)d_out;

    // 32 seq-blocks (128 sequences each) x 32 chunks = 1024 blocks of 128.
    iir_fused_kernel<<<(M_SEQ / 128) * NCH, 128>>>(x, A, B, y);
}

// round 15
// speedup vs baseline: 1.1654x; 1.1654x over previous
#include <cuda_runtime.h>
#include <cuda_bf16.h>

// IIR lfilter (order-8, 9 taps), DF2T, chunked parallelization.
// x: (64, 64, 8192) fp32 -> y = clip(lfilter(x, A, B), -1, 1)
//
// R14: revert R13's warm pipeline (measured regression: ping-pong WAR
// hazards + register pressure). Keep R12's validated structure (register
// FIR warmup, fused G table, WARM=192) and halve the per-chunk overhead:
// NCH=16 (CHUNK=512) cuts total warm issues and warm traffic by 2x
// (-16% total issues). R8 measured issue=44.8% at this occupancy
// (~3.5 CTAs/SM), so the rate should hold. launch_bounds(128,4).

#define T_LEN   8192
#define M_SEQ   4096
#define NCH     16         // chunks per sequence
#define CHUNK   512        // T_LEN / NCH
#define WARM    192        // FIR taps (0.95^192 ~ 5e-5 transient)
#define TT      16         // time-tile
#define STRIDE  130        // SMEM row stride (conflict-free under this lane map)

// One DF2T step. State z0..z7; unclamped y feeds the recurrence.
#define IIR_STEP(xv, yout)                                       \
    do {                                                         \
        float _iir_y = fmaf(b0, (xv), z0);                       \
        z0 = fmaf(-a1, _iir_y, fmaf(b1, (xv), z1));              \
        z1 = fmaf(-a2, _iir_y, fmaf(b2, (xv), z2));              \
        z2 = fmaf(-a3, _iir_y, fmaf(b3, (xv), z3));              \
        z3 = fmaf(-a4, _iir_y, fmaf(b4, (xv), z4));              \
        z4 = fmaf(-a5, _iir_y, fmaf(b5, (xv), z5));              \
        z5 = fmaf(-a6, _iir_y, fmaf(b6, (xv), z6));              \
        z6 = fmaf(-a7, _iir_y, fmaf(b7, (xv), z7));              \
        z7 = fmaf(-a8, _iir_y, b8 * (xv));                       \
        (yout) = _iir_y;                                         \
    } while (0)

__global__ __launch_bounds__(128, 4)
void iir_fused_kernel(const float* __restrict__ x,
                      const float* __restrict__ Ag,
                      const float* __restrict__ Bg,
                      float* __restrict__ y)
{
    __shared__ float  xs[TT * STRIDE];   // [time][seq] transpose tile
    __shared__ float  ys[TT * STRIDE];   // output tile; reused as state scratch
    __shared__ float4 gs03[WARM];        // G(d) states z0..z3
    __shared__ float4 gs47[WARM];        // G(d) states z4..z7

    const int tid   = threadIdx.x;                 // 0..127 = local sequence
    const int c     = blockIdx.x >> 5;             // chunk index 0..15 (block-uniform)
    const int mbase = (blockIdx.x & 31) << 7;      // 128 sequences per block

    // Lane map for tile I/O: thread -> (row base rl, time column col).
    const int rl  = tid >> 2;           // 0..31; rows rl + 32*i
    const int cj  = tid & 3;            // 0..3
    const int col = cj << 2;            // 0,4,8,12

    const float* xbase = x + (size_t)(mbase + rl) * T_LEN + col;
    float*       ybase = y + (size_t)(mbase + rl) * T_LEN + col;

    const int tout = c * CHUNK;
    const int tend = tout + CHUNK;

    float z0 = 0.f, z1 = 0.f, z2 = 0.f, z3 = 0.f,
          z4 = 0.f, z5 = 0.f, z6 = 0.f, z7 = 0.f;

    float4 pf[4];

    if (c > 0) {
        // ---- G table: impulse response of DF2T state, computed per block ----
        if (tid == 0) {
            const float ginv = 1.0f / Ag[0];
            float ga[9], gb[9];
#pragma unroll
            for (int i = 0; i < 9; i++) { ga[i] = Ag[i] * ginv; gb[i] = Bg[i] * ginv; }
            float gz[8];
            const float gy0 = gb[0];                       // impulse step
#pragma unroll
            for (int i = 0; i < 8; i++) gz[i] = gb[i + 1] - ga[i + 1] * gy0;
            gs03[0] = make_float4(gz[0], gz[1], gz[2], gz[3]);
            gs47[0] = make_float4(gz[4], gz[5], gz[6], gz[7]);
            for (int d = 1; d < WARM; d++) {
                const float yv = gz[0];                    // zero-input step
#pragma unroll
                for (int i = 0; i < 7; i++) gz[i] = gz[i + 1] - ga[i + 1] * yv;
                gz[7] = -ga[8] * yv;
                gs03[d] = make_float4(gz[0], gz[1], gz[2], gz[3]);
                gs47[d] = make_float4(gz[4], gz[5], gz[6], gz[7]);
            }
        }
        __syncthreads();

        // ---- Warm phase: register FIR over the loader's own data ----
        float acc[4][8];
#pragma unroll
        for (int i = 0; i < 4; i++)
#pragma unroll
            for (int s = 0; s < 8; s++) acc[i][s] = 0.f;

        const int tstart = tout - WARM;
        for (int t = tstart; t < tout; t += TT) {
#pragma unroll
            for (int i = 0; i < 4; i++)
                pf[i] = *reinterpret_cast<const float4*>(xbase + (size_t)i * 32 * T_LEN + t);

            const int dbase = tout - 1 - t - col;          // per-thread
#pragma unroll
            for (int k = 0; k < 4; k++) {
                const float4 g0 = gs03[dbase - k];         // 4 addrs/warp: 1 wf
                const float4 g1 = gs47[dbase - k];
#pragma unroll
                for (int i = 0; i < 4; i++) {
                    const float xv = reinterpret_cast<const float*>(&pf[i])[k];
                    acc[i][0] = fmaf(g0.x, xv, acc[i][0]);
                    acc[i][1] = fmaf(g0.y, xv, acc[i][1]);
                    acc[i][2] = fmaf(g0.z, xv, acc[i][2]);
                    acc[i][3] = fmaf(g0.w, xv, acc[i][3]);
                    acc[i][4] = fmaf(g1.x, xv, acc[i][4]);
                    acc[i][5] = fmaf(g1.y, xv, acc[i][5]);
                    acc[i][6] = fmaf(g1.z, xv, acc[i][6]);
                    acc[i][7] = fmaf(g1.w, xv, acc[i][7]);
                }
            }
        }

        // Butterfly all-reduce across the 4 col-lanes (lanes xor 1, xor 2).
#pragma unroll
        for (int i = 0; i < 4; i++)
#pragma unroll
            for (int s = 0; s < 8; s++) {
                acc[i][s] += __shfl_xor_sync(0xFFFFFFFFu, acc[i][s], 1);
                acc[i][s] += __shfl_xor_sync(0xFFFFFFFFu, acc[i][s], 2);
            }

        // Prefetch first emit tile while the exchange settles.
#pragma unroll
        for (int i = 0; i < 4; i++)
            pf[i] = *reinterpret_cast<const float4*>(xbase + (size_t)i * 32 * T_LEN + tout);

        // Exchange: states -> owner threads via ys scratch (ys[s][row]).
        if (cj == 0) {
#pragma unroll
            for (int i = 0; i < 4; i++)
#pragma unroll
                for (int s = 0; s < 8; s++)
                    ys[s * STRIDE + (rl + 32 * i)] = acc[i][s];
        }
        __syncthreads();
        z0 = ys[0 * STRIDE + tid];
        z1 = ys[1 * STRIDE + tid];
        z2 = ys[2 * STRIDE + tid];
        z3 = ys[3 * STRIDE + tid];
        z4 = ys[4 * STRIDE + tid];
        z5 = ys[5 * STRIDE + tid];
        z6 = ys[6 * STRIDE + tid];
        z7 = ys[7 * STRIDE + tid];

        // Stage first emit tile into xs.
#pragma unroll
        for (int i = 0; i < 4; i++) {
            const int r = rl + 32 * i;
            xs[(col + 0) * STRIDE + r] = pf[i].x;
            xs[(col + 1) * STRIDE + r] = pf[i].y;
            xs[(col + 2) * STRIDE + r] = pf[i].z;
            xs[(col + 3) * STRIDE + r] = pf[i].w;
        }
        __syncthreads();   // xs staged; all z reads done before ys is rewritten
    } else {
        // c == 0: zero state, stage tile at t=0.
#pragma unroll
        for (int i = 0; i < 4; i++)
            pf[i] = *reinterpret_cast<const float4*>(xbase + (size_t)i * 32 * T_LEN);
#pragma unroll
        for (int i = 0; i < 4; i++) {
            const int r = rl + 32 * i;
            xs[(col + 0) * STRIDE + r] = pf[i].x;
            xs[(col + 1) * STRIDE + r] = pf[i].y;
            xs[(col + 2) * STRIDE + r] = pf[i].z;
            xs[(col + 3) * STRIDE + r] = pf[i].w;
        }
        __syncthreads();
    }

    // Coefficients (normalized by A[0]) — loaded after warm to cut warm-phase
    // register pressure.
    const float inv = 1.0f / __ldg(&Ag[0]);
    const float a1 = __ldg(&Ag[1]) * inv;
    const float a2 = __ldg(&Ag[2]) * inv;
    const float a3 = __ldg(&Ag[3]) * inv;
    const float a4 = __ldg(&Ag[4]) * inv;
    const float a5 = __ldg(&Ag[5]) * inv;
    const float a6 = __ldg(&Ag[6]) * inv;
    const float a7 = __ldg(&Ag[7]) * inv;
    const float a8 = __ldg(&Ag[8]) * inv;
    const float b0 = __ldg(&Bg[0]) * inv;
    const float b1 = __ldg(&Bg[1]) * inv;
    const float b2 = __ldg(&Bg[2]) * inv;
    const float b3 = __ldg(&Bg[3]) * inv;
    const float b4 = __ldg(&Bg[4]) * inv;
    const float b5 = __ldg(&Bg[5]) * inv;
    const float b6 = __ldg(&Bg[6]) * inv;
    const float b7 = __ldg(&Bg[7]) * inv;
    const float b8 = __ldg(&Bg[8]) * inv;

    // ================= Emit phase: IIR over [tout, tend) =================
    for (int t = tout; t < tend; t += TT) {
        const int tp = (t + TT < tend) ? (t + TT) : tout;   // in-bounds clamp
#pragma unroll
        for (int i = 0; i < 4; i++)
            pf[i] = *reinterpret_cast<const float4*>(xbase + (size_t)i * 32 * T_LEN + tp);

#pragma unroll
        for (int tt = 0; tt < TT; tt++) {
            const float xv = xs[tt * STRIDE + tid];
            float yo;
            IIR_STEP(xv, yo);
            ys[tt * STRIDE + tid] = fminf(fmaxf(yo, -1.0f), 1.0f);
        }
        __syncthreads();   // ys complete; xs consumed

        // Coalesced output of this tile.
#pragma unroll
        for (int i = 0; i < 4; i++) {
            const int r = rl + 32 * i;
            float4 v;
            v.x = ys[(col + 0) * STRIDE + r];
            v.y = ys[(col + 1) * STRIDE + r];
            v.z = ys[(col + 2) * STRIDE + r];
            v.w = ys[(col + 3) * STRIDE + r];
            *reinterpret_cast<float4*>(ybase + (size_t)i * 32 * T_LEN + t) = v;
        }

        // Stage prefetched tile.
#pragma unroll
        for (int i = 0; i < 4; i++) {
            const int r = rl + 32 * i;
            xs[(col + 0) * STRIDE + r] = pf[i].x;
            xs[(col + 1) * STRIDE + r] = pf[i].y;
            xs[(col + 2) * STRIDE + r] = pf[i].z;
            xs[(col + 3) * STRIDE + r] = pf[i].w;
        }
        __syncthreads();
    }
}

extern "C" void kernel_launch(void* const* d_in, const int* in_sizes, int n_in,
                              void* d_out, int out_size)
{
    const float* x = (const float*)d_in[0];
    const float* A = (const float*)d_in[1];
    const float* B = (const float*)d_in[2];
    float*       y = (float*)d_out;

    // 32 seq-blocks (128 sequences each) x 16 chunks = 512 blocks of 128.
    iir_fused_kernel<<<(M_SEQ / 128) * NCH, 128>>>(x, A, B, y);
}